// round 7
// baseline (speedup 1.0000x reference)
#include <cuda_runtime.h>
#include <cuda_bf16.h>
#include <math.h>
#include <stdint.h>

// Laplace diagonal recurrence:
//   out[t, i, f] = e[i] * out[t-1, i, f] + decay[i] * inp[t, f]
// T = 2048, N_S = 108, F = 256, fp32.
//
// R7 (= R6 with compile fix): input staged through smem with a 6-stage
// cp.async.cg ring (8 rows/stage, ~40 rows in flight) so the recurrence loop
// has no global-load scoreboard waits. Block = 256 threads: fq 0..63 (float4
// lane), iq 0..3, 3 i-states each => GI=12 i per block, NIB=9. CHUNK=64,
// WARM=64. Grid = 9 x 32 = 288 blocks (~16 warps/SM). STG.128 evict-first.

constexpr int T_LEN  = 2048;
constexpr int F      = 256;
constexpr int NS     = 108;
constexpr int CHUNK  = 64;
constexpr int WARM   = 64;
constexpr int NCHUNK = T_LEN / CHUNK;   // 32
constexpr int GI     = 12;              // i-values per block
constexpr int NIB    = NS / GI;         // 9
constexpr int F4     = F / 4;           // 64 float4 per row
constexpr int SROWS  = 8;               // rows per stage
constexpr int NSTG   = 6;               // ring stages (6*8KB = 48KB smem)
constexpr int PRE    = 5;               // stages issued ahead
constexpr int THR    = 256;

typedef unsigned long long u64;
typedef unsigned int       u32;

__device__ __forceinline__ u64 fma2(u64 a, u64 b, u64 c) {
    u64 d;
    asm("fma.rn.f32x2 %0, %1, %2, %3;" : "=l"(d) : "l"(a), "l"(b), "l"(c));
    return d;
}
__device__ __forceinline__ u64 mul2(u64 a, u64 b) {
    u64 d;
    asm("mul.rn.f32x2 %0, %1, %2;" : "=l"(d) : "l"(a), "l"(b));
    return d;
}
__device__ __forceinline__ u64 pack2(float lo, float hi) {
    u64 d;
    asm("mov.b64 %0, {%1, %2};" : "=l"(d) : "f"(lo), "f"(hi));
    return d;
}

union V4 {
    float4 f;
    u64    u[2];
};

__device__ __forceinline__ void cp16(void* smem_ptr, const void* gptr) {
    u32 sa = (u32)__cvta_generic_to_shared(smem_ptr);
    asm volatile("cp.async.cg.shared.global [%0], [%1], 16;"
                 :: "r"(sa), "l"(gptr) : "memory");
}
__device__ __forceinline__ void cp_commit() {
    asm volatile("cp.async.commit_group;" ::: "memory");
}
template <int N>
__device__ __forceinline__ void cp_wait() {
    asm volatile("cp.async.wait_group %0;" :: "n"(N) : "memory");
}

__global__ __launch_bounds__(THR)
void laplace_kernel(const float* __restrict__ inp, float* __restrict__ out) {
    __shared__ float4 sbuf[NSTG * SROWS * F4];   // 48 KB

    const int tid = threadIdx.x;
    const int fq  = tid & 63;        // float4 lane
    const int iq  = tid >> 6;        // 0..3
    const int ib  = blockIdx.x;      // 0..8
    const int chunk = blockIdx.y;    // 0..31

    // Per-i constants in double precision (matches reference ~1e-7).
    u64 e2[3], d2[3];
    const double c = pow(20.0, 1.0 / 99.0) - 1.0;
    #pragma unroll
    for (int k = 0; k < 3; k++) {
        int i = ib * GI + iq * 3 + k;
        double tau = pow(1.0 + c, (double)(i - 4));
        double s   = 4.0 / tau;
        double ed  = exp(-s);
        float ef = (float)ed;
        float df = (float)((1.0 - ed) / s);
        e2[k] = pack2(ef, ef);
        d2[k] = pack2(df, df);
    }

    const int t_start = chunk * CHUNK;
    const int warm    = (t_start < WARM) ? t_start : WARM;  // 0 or 64
    const int t0      = t_start - warm;
    const int rows    = warm + CHUNK;                        // 64 or 128
    const int ns      = rows / SROWS;                        // 8 or 16

    const float4* __restrict__ gsrc = reinterpret_cast<const float4*>(inp)
                                      + (size_t)t0 * F4;

    // Stage copy: 8 rows x 64 float4 = 512 float4; 2 per thread.
    auto issue_stage = [&](int s) {
        const int buf = s % NSTG;
        #pragma unroll
        for (int j = 0; j < 2; j++) {
            int q   = tid * 2 + j;       // 0..511
            int r   = q >> 6;            // row in stage
            int col = q & 63;
            cp16(&sbuf[(buf * SROWS + r) * F4 + col],
                 gsrc + (size_t)(s * SROWS + r) * F4 + col);
        }
        cp_commit();
    };

    // Prologue: issue PRE stages (or fewer).
    #pragma unroll
    for (int s = 0; s < PRE; s++) {
        if (s < ns) issue_stage(s);
        else        cp_commit();   // keep group count uniform
    }

    // Scaled states: st' = e*st' + x;  out = dcy * st'.
    u64 st[3][2];
    #pragma unroll
    for (int k = 0; k < 3; k++) { st[k][0] = 0ull; st[k][1] = 0ull; }

    float4* op = reinterpret_cast<float4*>(out)
               + ((size_t)t_start * NS + (size_t)(ib * GI + iq * 3)) * F4 + fq;

    for (int s = 0; s < ns; s++) {
        cp_wait<PRE - 1>();          // stage s landed
        __syncthreads();             // all warps done with stage s-1's buffer
        if (s + PRE < ns) issue_stage(s + PRE);
        else              cp_commit();

        const float4* srow = &sbuf[(s % NSTG) * SROWS * F4 + fq];
        if (s * SROWS >= warm) {
            // storing stage
            #pragma unroll
            for (int r = 0; r < SROWS; r++) {
                V4 x; x.f = srow[r * F4];
                #pragma unroll
                for (int k = 0; k < 3; k++) {
                    st[k][0] = fma2(e2[k], st[k][0], x.u[0]);
                    st[k][1] = fma2(e2[k], st[k][1], x.u[1]);
                    V4 o;
                    o.u[0] = mul2(d2[k], st[k][0]);
                    o.u[1] = mul2(d2[k], st[k][1]);
                    __stcs(&op[k * F4], o.f);
                }
                op += NS * F4;
            }
        } else {
            // warm-up stage (no stores)
            #pragma unroll
            for (int r = 0; r < SROWS; r++) {
                V4 x; x.f = srow[r * F4];
                #pragma unroll
                for (int k = 0; k < 3; k++) {
                    st[k][0] = fma2(e2[k], st[k][0], x.u[0]);
                    st[k][1] = fma2(e2[k], st[k][1], x.u[1]);
                }
            }
        }
    }
}

extern "C" void kernel_launch(void* const* d_in, const int* in_sizes, int n_in,
                              void* d_out, int out_size) {
    const float* inp = (const float*)d_in[0];
    float* out       = (float*)d_out;
    dim3 grid(NIB, NCHUNK);   // 9 x 32 = 288 blocks
    laplace_kernel<<<grid, THR>>>(inp, out);
}